// round 10
// baseline (speedup 1.0000x reference)
#include <cuda_runtime.h>

typedef unsigned long long ull;

// ---------------- SLAYER constants (fp32-rounded from the reference doubles) ----
#define THETA   10.0f
#define D_SR    0.9048374180359595f     // exp(-1/10)
#define B_SR    0.2718281828459045f     // e/10
#define D_REF   0.36787944117144233f    // exp(-1)
#define A_REF  -54.365636569180902f     // -2*10*e
#define GAIN    11.0f                   // 1.1 * theta

// ---------------- packed fp32x2 helpers (Blackwell FFMA2 path) ------------------
__device__ __forceinline__ void fma2(ull& acc, ull a, ull b) {
    asm("fma.rn.f32x2 %0, %1, %2, %0;" : "+l"(acc) : "l"(a), "l"(b));
}
__device__ __forceinline__ ull pk(float lo, float hi) {
    ull r; asm("mov.b64 %0, {%1,%2};" : "=l"(r) : "f"(lo), "f"(hi)); return r;
}
__device__ __forceinline__ float2 upk(ull v) {
    float2 r; asm("mov.b64 {%0,%1}, %2;" : "=f"(r.x), "=f"(r.y) : "l"(v)); return r;
}

// ---------------- static scratch (no allocation allowed) ------------------------
// BUFA holds conv outputs. conv1/conv2 write POOLED-QUAD layout:
//   [nc][t][oh*WO+ow][4]  (quad = {r0c0, r0c1, r1c0, r1c1} of the 2x2 pool window)
__device__ __align__(256) float BUFA[30105600];  // max: U1-quad [8*16][300][196][4]
__device__ __align__(256) float BUFB[7526400];   // max: P2 [8,16,300,196]
__device__ __align__(256) ull   WT2D[4608];      // conv2 weights, dup'd, [k144][oc32]
__device__ __align__(256) ull   WT3D[18432];     // conv3 weights, dup'd, [k288][oc64]

// ---------------- K0: transpose + duplicate weights to packed lane-major --------
__global__ void wprep_kernel(const float* __restrict__ w2, const float* __restrict__ w3) {
    int i = blockIdx.x * 256 + threadIdx.x;
    if (i < 4608)  { int oc = i / 144, k = i % 144; WT2D[k * 32 + oc] = pk(w2[i], w2[i]); }
    if (i < 18432) { int oc = i / 288, k = i % 288; WT3D[k * 64 + oc] = pk(w3[i], w3[i]); }
}

// ---------------- K1: psp of input + transpose [n,hw,T] -> [n,T,hw] -------------
__global__ void psp_in_kernel(const float* __restrict__ x) {
    int tid = blockIdx.x * blockDim.x + threadIdx.x;
    if (tid >= 8 * 900) return;
    int n = tid / 900, hw = tid % 900;
    const float4* xp4 = reinterpret_cast<const float4*>(x + (size_t)tid * 300);
    float* yp = BUFB + (size_t)n * 300 * 900 + hw;
    float p = 0.f, q = 0.f;

    float4 ring[4];
    #pragma unroll
    for (int i = 0; i < 4; i++) ring[i] = xp4[i];
    for (int cb = 0; cb < 75; cb += 4) {
        #pragma unroll
        for (int j = 0; j < 4; j++) {
            int c = cb + j;
            if (c < 75) {
                float4 cur = ring[j];
                if (c + 4 < 75) ring[j] = xp4[c + 4];
                int t = 4 * c;
                q = D_SR * (q + p); p = D_SR * p + cur.x; yp[(size_t)(t+0) * 900] = B_SR * q;
                q = D_SR * (q + p); p = D_SR * p + cur.y; yp[(size_t)(t+1) * 900] = B_SR * q;
                q = D_SR * (q + p); p = D_SR * p + cur.z; yp[(size_t)(t+2) * 900] = B_SR * q;
                q = D_SR * (q + p); p = D_SR * p + cur.w; yp[(size_t)(t+3) * 900] = B_SR * q;
            }
        }
    }
}

// ---------------- K2: conv1 1->16, 5x5 pad1, 30x30 -> 28x28, FFMA2 --------------
// 448 thr = 14 warps; warp w -> rows {2w,2w+1}; lane: oc=l&15, rowsub=l>>4
// Output written in pooled-quad layout: [(n*16+oc)][t][oh*14+p][4] + rowsub*2
__global__ void __launch_bounds__(448) conv1_kernel(const float* __restrict__ w) {
    __shared__ float sIn[32 * 36];   // padded 32 rows x 36-float stride
    __shared__ float sW[400];
    int t = blockIdx.x, n = blockIdx.y, tid = threadIdx.x;

    for (int i = tid; i < 32 * 36; i += 448) sIn[i] = 0.f;
    for (int i = tid; i < 400;     i += 448) sW[i] = w[i];
    __syncthreads();
    const float* src = BUFB + ((size_t)n * 300 + t) * 900;
    for (int i = tid; i < 900; i += 448) {
        int ih = i / 30, iw = i % 30;
        sIn[(ih + 1) * 36 + (iw + 1)] = src[i];
    }
    __syncthreads();

    int wp = tid >> 5, l = tid & 31;
    int oc = l & 15, rsub = l >> 4, orow = 2 * wp + rsub;

    float wr[25];
    #pragma unroll
    for (int k = 0; k < 25; k++) wr[k] = sW[oc * 25 + k];

    ull acc[14];
    #pragma unroll
    for (int p = 0; p < 14; p++) acc[p] = 0ull;

    #pragma unroll
    for (int kh = 0; kh < 5; kh++) {
        const float* rp = &sIn[(orow + kh) * 36];
        float4 f[8];
        #pragma unroll
        for (int i = 0; i < 8; i++) f[i] = *reinterpret_cast<const float4*>(rp + i * 4);
        float a[32];
        #pragma unroll
        for (int i = 0; i < 8; i++) {
            a[i*4+0]=f[i].x; a[i*4+1]=f[i].y; a[i*4+2]=f[i].z; a[i*4+3]=f[i].w;
        }
        ull A[16], S[15];
        #pragma unroll
        for (int p = 0; p < 16; p++) A[p] = pk(a[2*p], a[2*p+1]);
        #pragma unroll
        for (int p = 0; p < 15; p++) S[p] = pk(a[2*p+1], a[2*p+2]);

        #pragma unroll
        for (int kw = 0; kw < 5; kw++) {
            ull wq = pk(wr[kh*5+kw], wr[kh*5+kw]);
            #pragma unroll
            for (int p = 0; p < 14; p++) {
                ull op = (kw == 0) ? A[p] : (kw == 1) ? S[p] : (kw == 2) ? A[p+1]
                         : (kw == 3) ? S[p+1] : A[p+2];
                fma2(acc[p], op, wq);
            }
        }
    }
    // pooled-quad store: quad index = (orow/2)*14 + p, half = rsub
    float* qb = BUFA + (((size_t)(n*16+oc)*300 + t) * 196 + (orow >> 1) * 14) * 4 + rsub * 2;
    #pragma unroll
    for (int p = 0; p < 14; p++)
        *reinterpret_cast<ull*>(qb + p * 4) = acc[p];
}

// ---------------- fused pool layer (reference-exact op order) -------------------
// input: pooled-quad BUFA [nc][t][howo][4]; ring prefetch 12 timesteps ahead
__global__ void poolfuse_kernel(int howo, int total) {
    int tid = blockIdx.x * blockDim.x + threadIdx.x;
    if (tid >= total) return;
    int nc = tid / howo, hw = tid % howo;
    const float4* ub = reinterpret_cast<const float4*>(BUFA) + (size_t)nc * 300 * howo + hw;
    float* ob = BUFB + (size_t)nc * 300 * howo + hw;

    float pa=0,qa=0, pb=0,qb=0, pc=0,qc=0, pd=0,qd=0;
    float Pa=0,Qa=0, Pb=0,Qb=0, Pc=0,Qc=0, Pd=0,Qd=0;
    float p2=0,q2=0, p3=0,q3=0;

    float4 ring[12];
    #pragma unroll
    for (int i = 0; i < 12; i++) ring[i] = ub[(size_t)i * howo];

    for (int tb = 0; tb < 300; tb += 12) {
        #pragma unroll
        for (int j = 0; j < 12; j++) {
            int t = tb + j;
            if (t < 300) {
                float4 cur = ring[j];
                if (t + 12 < 300) ring[j] = ub[(size_t)(t + 12) * howo];

                qa = D_REF*(qa+pa); float sa = (cur.x + A_REF*qa >= THETA) ? 1.f : 0.f; pa = D_REF*pa + sa;
                qb = D_REF*(qb+pb); float sb = (cur.y + A_REF*qb >= THETA) ? 1.f : 0.f; pb = D_REF*pb + sb;
                qc = D_REF*(qc+pc); float sc = (cur.z + A_REF*qc >= THETA) ? 1.f : 0.f; pc = D_REF*pc + sc;
                qd = D_REF*(qd+pd); float sd = (cur.w + A_REF*qd >= THETA) ? 1.f : 0.f; pd = D_REF*pd + sd;

                Qa = D_SR*(Qa+Pa); Pa = D_SR*Pa + sa;
                Qb = D_SR*(Qb+Pb); Pb = D_SR*Pb + sb;
                Qc = D_SR*(Qc+Pc); Pc = D_SR*Pc + sc;
                Qd = D_SR*(Qd+Pd); Pd = D_SR*Pd + sd;
                float vv = GAIN * (((B_SR*Qa + B_SR*Qb) + B_SR*Qc) + B_SR*Qd);

                q2 = D_REF*(q2+p2); float s = (vv + A_REF*q2 >= THETA) ? 1.f : 0.f; p2 = D_REF*p2 + s;
                q3 = D_SR*(q3+p3);  p3 = D_SR*p3 + s;
                ob[(size_t)t * howo] = B_SR * q3;
            }
        }
    }
}

// ---------------- K4: conv2 16->32, 3x3 pad1, 14x14, oc-lanes + FFMA2 -----------
// 224 thr = 7 warps; warp w -> rows {2w,2w+1}; lane = oc; inputs broadcast-read
// Weights pre-duplicated (ull smem, LDS.64, zero packing MOVs)
__global__ void __launch_bounds__(224) conv2_kernel() {
    __shared__ float sIn[16 * 256];   // [ic][row16][col16]
    __shared__ ull   sW[4608];        // [k144][oc32], dup'd pairs
    int t = blockIdx.x, n = blockIdx.y, tid = threadIdx.x;

    for (int i = tid; i < 4608; i += 224) sW[i] = WT2D[i];
    for (int i = tid; i < 4096; i += 224) sIn[i] = 0.f;
    __syncthreads();
    for (int i = tid; i < 16 * 196; i += 224) {
        int c = i / 196, idx = i % 196, ih = idx / 14, iw = idx % 14;
        sIn[c * 256 + (ih + 1) * 16 + (iw + 1)] =
            BUFB[((size_t)(n * 16 + c) * 300 + t) * 196 + idx];
    }
    __syncthreads();

    int wp = tid >> 5, oc = tid & 31;
    ull acc0[7], acc1[7];
    #pragma unroll
    for (int p = 0; p < 7; p++) { acc0[p] = 0ull; acc1[p] = 0ull; }

    for (int ic = 0; ic < 16; ic++) {
        ull wq[9];
        #pragma unroll
        for (int k = 0; k < 9; k++) wq[k] = sW[(ic * 9 + k) * 32 + oc];

        const float* base = &sIn[ic * 256 + (2 * wp) * 16];
        #pragma unroll
        for (int j = 0; j < 4; j++) {
            const float* rp = base + j * 16;
            float4 f0 = *reinterpret_cast<const float4*>(rp);
            float4 f1 = *reinterpret_cast<const float4*>(rp + 4);
            float4 f2 = *reinterpret_cast<const float4*>(rp + 8);
            float4 f3 = *reinterpret_cast<const float4*>(rp + 12);
            ull A[8], S[7];
            A[0]=pk(f0.x,f0.y); A[1]=pk(f0.z,f0.w); A[2]=pk(f1.x,f1.y); A[3]=pk(f1.z,f1.w);
            A[4]=pk(f2.x,f2.y); A[5]=pk(f2.z,f2.w); A[6]=pk(f3.x,f3.y); A[7]=pk(f3.z,f3.w);
            S[0]=pk(f0.y,f0.z); S[1]=pk(f0.w,f1.x); S[2]=pk(f1.y,f1.z); S[3]=pk(f1.w,f2.x);
            S[4]=pk(f2.y,f2.z); S[5]=pk(f2.w,f3.x); S[6]=pk(f3.y,f3.z);

            if (j <= 2) {   // out row 2w, kh = j
                int kb = j * 3;
                #pragma unroll
                for (int p = 0; p < 7; p++) fma2(acc0[p], A[p],   wq[kb+0]);
                #pragma unroll
                for (int p = 0; p < 7; p++) fma2(acc0[p], S[p],   wq[kb+1]);
                #pragma unroll
                for (int p = 0; p < 7; p++) fma2(acc0[p], A[p+1], wq[kb+2]);
            }
            if (j >= 1) {   // out row 2w+1, kh = j-1
                int kb = (j - 1) * 3;
                #pragma unroll
                for (int p = 0; p < 7; p++) fma2(acc1[p], A[p],   wq[kb+0]);
                #pragma unroll
                for (int p = 0; p < 7; p++) fma2(acc1[p], S[p],   wq[kb+1]);
                #pragma unroll
                for (int p = 0; p < 7; p++) fma2(acc1[p], A[p+1], wq[kb+2]);
            }
        }
    }
    // pooled-quad store: quad index = wp*7 + p; full float4 per window
    float4* qb = reinterpret_cast<float4*>(BUFA) +
                 (((size_t)(n * 32 + oc) * 300 + t) * 49 + wp * 7);
    #pragma unroll
    for (int p = 0; p < 7; p++) {
        float2 lo = upk(acc0[p]), hi = upk(acc1[p]);
        qb[p] = make_float4(lo.x, lo.y, hi.x, hi.y);
    }
}

// ---------------- K6: conv3 32->64, 3x3 pad1, 7x7, 2 timesteps/block ------------
// 224 thr = 7 warps; warp = out row; lane -> oc pair; dup'd weights via LDG.64
__global__ void __launch_bounds__(224) conv3_kernel() {
    __shared__ float sIn[2][32][108];   // [tt][ic][9 rows x 12-col stride]
    int tp = blockIdx.x, n = blockIdx.y, tid = threadIdx.x;
    int t0 = 2 * tp;

    for (int i = tid; i < 2 * 32 * 108; i += 224) ((float*)sIn)[i] = 0.f;
    __syncthreads();
    for (int i = tid; i < 2 * 32 * 49; i += 224) {
        int tt = i / (32 * 49), r = i % (32 * 49);
        int c = r / 49, idx = r % 49, ih = idx / 7, iw = idx % 7;
        sIn[tt][c][(ih + 1) * 12 + (iw + 1)] =
            BUFB[((size_t)(n * 32 + c) * 300 + t0 + tt) * 49 + idx];
    }
    __syncthreads();

    int wp = tid >> 5, l = tid & 31;
    ull acc[2][2][4];
    #pragma unroll
    for (int tt = 0; tt < 2; tt++)
        #pragma unroll
        for (int s = 0; s < 2; s++)
            #pragma unroll
            for (int p = 0; p < 4; p++) acc[tt][s][p] = 0ull;

    for (int ic = 0; ic < 32; ic++) {
        ull wa[9], wb[9];
        #pragma unroll
        for (int k = 0; k < 9; k++) {
            const ull* wp64 = &WT3D[(ic * 9 + k) * 64 + 2 * l];
            wa[k] = __ldg(wp64);
            wb[k] = __ldg(wp64 + 1);
        }
        #pragma unroll
        for (int tt = 0; tt < 2; tt++) {
            const float* base = &sIn[tt][ic][wp * 12];
            #pragma unroll
            for (int j = 0; j < 3; j++) {     // kh = j
                const float* rp = base + j * 12;
                float4 f0 = *reinterpret_cast<const float4*>(rp);
                float4 f1 = *reinterpret_cast<const float4*>(rp + 4);
                float4 f2 = *reinterpret_cast<const float4*>(rp + 8);
                ull A0=pk(f0.x,f0.y), A1=pk(f0.z,f0.w), A2=pk(f1.x,f1.y),
                    A3=pk(f1.z,f1.w), A4=pk(f2.x,f2.y);
                ull S0=pk(f0.y,f0.z), S1=pk(f0.w,f1.x), S2=pk(f1.y,f1.z), S3=pk(f1.w,f2.x);
                int kb = j * 3;
                ull* a0 = acc[tt][0]; ull* a1 = acc[tt][1];
                fma2(a0[0],A0,wa[kb+0]); fma2(a0[1],A1,wa[kb+0]); fma2(a0[2],A2,wa[kb+0]); fma2(a0[3],A3,wa[kb+0]);
                fma2(a0[0],S0,wa[kb+1]); fma2(a0[1],S1,wa[kb+1]); fma2(a0[2],S2,wa[kb+1]); fma2(a0[3],S3,wa[kb+1]);
                fma2(a0[0],A1,wa[kb+2]); fma2(a0[1],A2,wa[kb+2]); fma2(a0[2],A3,wa[kb+2]); fma2(a0[3],A4,wa[kb+2]);
                fma2(a1[0],A0,wb[kb+0]); fma2(a1[1],A1,wb[kb+0]); fma2(a1[2],A2,wb[kb+0]); fma2(a1[3],A3,wb[kb+0]);
                fma2(a1[0],S0,wb[kb+1]); fma2(a1[1],S1,wb[kb+1]); fma2(a1[2],S2,wb[kb+1]); fma2(a1[3],S3,wb[kb+1]);
                fma2(a1[0],A1,wb[kb+2]); fma2(a1[1],A2,wb[kb+2]); fma2(a1[2],A3,wb[kb+2]); fma2(a1[3],A4,wb[kb+2]);
            }
        }
    }
    #pragma unroll
    for (int tt = 0; tt < 2; tt++)
        #pragma unroll
        for (int s = 0; s < 2; s++) {
            float* dst = BUFA + ((size_t)(n * 64 + 2 * l + s) * 300 + t0 + tt) * 49 + wp * 7;
            float2 v0 = upk(acc[tt][s][0]), v1 = upk(acc[tt][s][1]);
            float2 v2 = upk(acc[tt][s][2]), v3 = upk(acc[tt][s][3]);
            dst[0]=v0.x; dst[1]=v0.y; dst[2]=v1.x; dst[3]=v1.y;
            dst[4]=v2.x; dst[5]=v2.y; dst[6]=v3.x;
        }
}

// ---------------- K7: spike(u5) then psp -> P5, in place; ring prefetch ---------
__global__ void spikepsp_kernel(int HW, int total) {
    int tid = blockIdx.x * blockDim.x + threadIdx.x;
    if (tid >= total) return;
    int slab = tid / HW, hw = tid % HW;
    float* bp = BUFA + (size_t)slab * 300 * HW + hw;
    float pr = 0.f, qr = 0.f, pp = 0.f, qp = 0.f;

    float ring[8];
    #pragma unroll
    for (int i = 0; i < 8; i++) ring[i] = bp[(size_t)i * HW];

    for (int tb = 0; tb < 300; tb += 8) {
        #pragma unroll
        for (int j = 0; j < 8; j++) {
            int t = tb + j;
            if (t < 300) {
                float cur = ring[j];
                if (t + 8 < 300) ring[j] = bp[(size_t)(t + 8) * HW];
                qr = D_REF * (qr + pr);
                float s = (cur + A_REF * qr >= THETA) ? 1.f : 0.f;
                pr = D_REF * pr + s;
                qp = D_SR * (qp + pp);
                pp = D_SR * pp + s;
                bp[(size_t)t * HW] = B_SR * qp;
            }
        }
    }
}

// ---------------- K8: dense 64*7*7 -> 10, 4 timesteps/block ---------------------
__global__ void __launch_bounds__(320) dense_kernel(const float* __restrict__ w,
                                                    float* __restrict__ out) {
    __shared__ float sX[4][3136];
    int tp = blockIdx.x, n = blockIdx.y, tid = threadIdx.x;
    int t0 = 4 * tp;
    for (int i = tid; i < 4 * 3136; i += 320) {
        int tt = i / 3136, j = i % 3136, c = j / 49, hw = j % 49;
        sX[tt][j] = BUFA[((size_t)(n * 64 + c) * 300 + t0 + tt) * 49 + hw];
    }
    __syncthreads();
    int wp = tid / 32, lane = tid % 32;
    const float* wrow = w + (size_t)wp * 3136;
    float s0 = 0.f, s1 = 0.f, s2 = 0.f, s3 = 0.f;
    #pragma unroll
    for (int k = 0; k < 98; k++) {
        int idx = lane + k * 32;
        float wv = __ldg(wrow + idx);
        s0 += sX[0][idx] * wv;
        s1 += sX[1][idx] * wv;
        s2 += sX[2][idx] * wv;
        s3 += sX[3][idx] * wv;
    }
    #pragma unroll
    for (int o = 16; o > 0; o >>= 1) {
        s0 += __shfl_down_sync(0xffffffff, s0, o);
        s1 += __shfl_down_sync(0xffffffff, s1, o);
        s2 += __shfl_down_sync(0xffffffff, s2, o);
        s3 += __shfl_down_sync(0xffffffff, s3, o);
    }
    if (lane == 0) {
        float* op = out + (size_t)n * 3000 + wp * 300 + t0;
        op[0] = s0; op[1] = s1; op[2] = s2; op[3] = s3;
    }
}

// ---------------- K9: final spike, in place on d_out; float4 ring ---------------
__global__ void spike_out_kernel(float* __restrict__ out) {
    int tid = threadIdx.x;
    if (tid >= 80) return;
    float4* bp4 = reinterpret_cast<float4*>(out + (size_t)tid * 300);
    float p = 0.f, q = 0.f;

    float4 ring[4];
    #pragma unroll
    for (int i = 0; i < 4; i++) ring[i] = bp4[i];
    for (int cb = 0; cb < 75; cb += 4) {
        #pragma unroll
        for (int j = 0; j < 4; j++) {
            int c = cb + j;
            if (c < 75) {
                float4 cur = ring[j];
                if (c + 4 < 75) ring[j] = bp4[c + 4];
                float4 so;
                q = D_REF*(q+p); so.x = (cur.x + A_REF*q >= THETA) ? 1.f : 0.f; p = D_REF*p + so.x;
                q = D_REF*(q+p); so.y = (cur.y + A_REF*q >= THETA) ? 1.f : 0.f; p = D_REF*p + so.y;
                q = D_REF*(q+p); so.z = (cur.z + A_REF*q >= THETA) ? 1.f : 0.f; p = D_REF*p + so.z;
                q = D_REF*(q+p); so.w = (cur.w + A_REF*q >= THETA) ? 1.f : 0.f; p = D_REF*p + so.w;
                bp4[c] = so;
            }
        }
    }
}

// ---------------- launcher ------------------------------------------------------
extern "C" void kernel_launch(void* const* d_in, const int* in_sizes, int n_in,
                              void* d_out, int out_size) {
    const float* x   = (const float*)d_in[0];   // [8,1,30,30,300]
    const float* w1  = (const float*)d_in[1];   // [16,1,5,5]
    const float* w2  = (const float*)d_in[2];   // [32,16,3,3]
    const float* w3  = (const float*)d_in[3];   // [64,32,3,3]
    const float* wfc = (const float*)d_in[4];   // [10,64,7,7]
    float* out = (float*)d_out;                 // [8,10,300]

    dim3 gconv(300, 8);
    dim3 ghalf(150, 8);
    dim3 gquar(75, 8);

    wprep_kernel<<<72, 256>>>(w2, w3);
    psp_in_kernel<<<29, 256>>>(x);                       // P0 -> BUFB
    conv1_kernel<<<gconv, 448>>>(w1);                    // U1 quads -> BUFA
    poolfuse_kernel<<<392, 64>>>(196, 8 * 16 * 196);     // P2 -> BUFB
    conv2_kernel<<<gconv, 224>>>();                      // U3 quads -> BUFA
    poolfuse_kernel<<<196, 64>>>(49, 8 * 32 * 49);       // P4 -> BUFB
    conv3_kernel<<<ghalf, 224>>>();                      // U5 -> BUFA
    spikepsp_kernel<<<392, 64>>>(49, 8 * 64 * 49);       // P5 in place
    dense_kernel<<<gquar, 320>>>(wfc, out);
    spike_out_kernel<<<1, 96>>>(out);
}

// round 11
// speedup vs baseline: 1.1299x; 1.1299x over previous
#include <cuda_runtime.h>

typedef unsigned long long ull;

// ---------------- SLAYER constants (fp32-rounded from the reference doubles) ----
#define THETA   10.0f
#define D_SR    0.9048374180359595f     // exp(-1/10)
#define B_SR    0.2718281828459045f     // e/10
#define D_REF   0.36787944117144233f    // exp(-1)
#define A_REF  -54.365636569180902f     // -2*10*e
#define GAIN    11.0f                   // 1.1 * theta

// ---------------- packed fp32x2 helpers (Blackwell FFMA2 path) ------------------
__device__ __forceinline__ void fma2(ull& acc, ull a, ull b) {
    asm("fma.rn.f32x2 %0, %1, %2, %0;" : "+l"(acc) : "l"(a), "l"(b));
}
__device__ __forceinline__ ull pk(float lo, float hi) {
    ull r; asm("mov.b64 %0, {%1,%2};" : "=l"(r) : "f"(lo), "f"(hi)); return r;
}
__device__ __forceinline__ float2 upk(ull v) {
    float2 r; asm("mov.b64 {%0,%1}, %2;" : "=f"(r.x), "=f"(r.y) : "l"(v)); return r;
}

// ---------------- static scratch (no allocation allowed) ------------------------
// BUFA holds conv outputs. conv1/conv2 write POOLED-QUAD layout:
//   [nc][t][oh*WO+ow][4]  (quad = {r0c0, r0c1, r1c0, r1c1} of the 2x2 pool window)
__device__ __align__(256) float BUFA[30105600];  // max: U1-quad [8*16][300][196][4]
__device__ __align__(256) float BUFB[7526400];   // max: P2 [8,16,300,196]
__device__ __align__(256) float WT2[4608];       // conv2 weights, [k144][oc32]
__device__ __align__(256) float WT3[18432];      // conv3 weights, [k288][oc64]

// ---------------- K0: transpose weights to lane-major layouts -------------------
__global__ void wprep_kernel(const float* __restrict__ w2, const float* __restrict__ w3) {
    int i = blockIdx.x * 256 + threadIdx.x;
    if (i < 4608)  { int oc = i / 144, k = i % 144; WT2[k * 32 + oc] = w2[i]; }
    if (i < 18432) { int oc = i / 288, k = i % 288; WT3[k * 64 + oc] = w3[i]; }
}

// ---------------- K1: psp of input + transpose [n,hw,T] -> [n,T,hw] -------------
__global__ void psp_in_kernel(const float* __restrict__ x) {
    int tid = blockIdx.x * blockDim.x + threadIdx.x;
    if (tid >= 8 * 900) return;
    int n = tid / 900, hw = tid % 900;
    const float4* xp4 = reinterpret_cast<const float4*>(x + (size_t)tid * 300);
    float* yp = BUFB + (size_t)n * 300 * 900 + hw;
    float p = 0.f, q = 0.f;

    float4 ring[4];
    #pragma unroll
    for (int i = 0; i < 4; i++) ring[i] = xp4[i];
    for (int cb = 0; cb < 75; cb += 4) {
        #pragma unroll
        for (int j = 0; j < 4; j++) {
            int c = cb + j;
            if (c < 75) {
                float4 cur = ring[j];
                if (c + 4 < 75) ring[j] = xp4[c + 4];
                int t = 4 * c;
                q = D_SR * (q + p); p = D_SR * p + cur.x; yp[(size_t)(t+0) * 900] = B_SR * q;
                q = D_SR * (q + p); p = D_SR * p + cur.y; yp[(size_t)(t+1) * 900] = B_SR * q;
                q = D_SR * (q + p); p = D_SR * p + cur.z; yp[(size_t)(t+2) * 900] = B_SR * q;
                q = D_SR * (q + p); p = D_SR * p + cur.w; yp[(size_t)(t+3) * 900] = B_SR * q;
            }
        }
    }
}

// ---------------- K2: conv1 1->16, 5x5 pad1, 30x30 -> 28x28, FFMA2 --------------
// 448 thr = 14 warps; warp w -> rows {2w,2w+1}; lane: oc=l&15, rowsub=l>>4
// Output written in pooled-quad layout: [(n*16+oc)][t][oh*14+p][4] + rowsub*2
__global__ void __launch_bounds__(448) conv1_kernel(const float* __restrict__ w) {
    __shared__ float sIn[32 * 36];   // padded 32 rows x 36-float stride
    __shared__ float sW[400];
    int t = blockIdx.x, n = blockIdx.y, tid = threadIdx.x;

    for (int i = tid; i < 32 * 36; i += 448) sIn[i] = 0.f;
    for (int i = tid; i < 400;     i += 448) sW[i] = w[i];
    __syncthreads();
    const float* src = BUFB + ((size_t)n * 300 + t) * 900;
    for (int i = tid; i < 900; i += 448) {
        int ih = i / 30, iw = i % 30;
        sIn[(ih + 1) * 36 + (iw + 1)] = src[i];
    }
    __syncthreads();

    int wp = tid >> 5, l = tid & 31;
    int oc = l & 15, rsub = l >> 4, orow = 2 * wp + rsub;

    float wr[25];
    #pragma unroll
    for (int k = 0; k < 25; k++) wr[k] = sW[oc * 25 + k];

    ull acc[14];
    #pragma unroll
    for (int p = 0; p < 14; p++) acc[p] = 0ull;

    #pragma unroll
    for (int kh = 0; kh < 5; kh++) {
        const float* rp = &sIn[(orow + kh) * 36];
        float4 f[8];
        #pragma unroll
        for (int i = 0; i < 8; i++) f[i] = *reinterpret_cast<const float4*>(rp + i * 4);
        float a[32];
        #pragma unroll
        for (int i = 0; i < 8; i++) {
            a[i*4+0]=f[i].x; a[i*4+1]=f[i].y; a[i*4+2]=f[i].z; a[i*4+3]=f[i].w;
        }
        ull A[16], S[15];
        #pragma unroll
        for (int p = 0; p < 16; p++) A[p] = pk(a[2*p], a[2*p+1]);
        #pragma unroll
        for (int p = 0; p < 15; p++) S[p] = pk(a[2*p+1], a[2*p+2]);

        #pragma unroll
        for (int kw = 0; kw < 5; kw++) {
            ull wq = pk(wr[kh*5+kw], wr[kh*5+kw]);
            #pragma unroll
            for (int p = 0; p < 14; p++) {
                ull op = (kw == 0) ? A[p] : (kw == 1) ? S[p] : (kw == 2) ? A[p+1]
                         : (kw == 3) ? S[p+1] : A[p+2];
                fma2(acc[p], op, wq);
            }
        }
    }
    // pooled-quad store: quad index = (orow/2)*14 + p, half = rsub
    float* qb = BUFA + (((size_t)(n*16+oc)*300 + t) * 196 + (orow >> 1) * 14) * 4 + rsub * 2;
    #pragma unroll
    for (int p = 0; p < 14; p++)
        *reinterpret_cast<ull*>(qb + p * 4) = acc[p];
}

// ---------------- fused pool layer (reference-exact op order) -------------------
// input: pooled-quad BUFA [nc][t][howo][4]; ring prefetch 12 timesteps ahead
__global__ void poolfuse_kernel(int howo, int total) {
    int tid = blockIdx.x * blockDim.x + threadIdx.x;
    if (tid >= total) return;
    int nc = tid / howo, hw = tid % howo;
    const float4* ub = reinterpret_cast<const float4*>(BUFA) + (size_t)nc * 300 * howo + hw;
    float* ob = BUFB + (size_t)nc * 300 * howo + hw;

    float pa=0,qa=0, pb=0,qb=0, pc=0,qc=0, pd=0,qd=0;
    float Pa=0,Qa=0, Pb=0,Qb=0, Pc=0,Qc=0, Pd=0,Qd=0;
    float p2=0,q2=0, p3=0,q3=0;

    float4 ring[12];
    #pragma unroll
    for (int i = 0; i < 12; i++) ring[i] = ub[(size_t)i * howo];

    for (int tb = 0; tb < 300; tb += 12) {
        #pragma unroll
        for (int j = 0; j < 12; j++) {
            int t = tb + j;
            if (t < 300) {
                float4 cur = ring[j];
                if (t + 12 < 300) ring[j] = ub[(size_t)(t + 12) * howo];

                qa = D_REF*(qa+pa); float sa = (cur.x + A_REF*qa >= THETA) ? 1.f : 0.f; pa = D_REF*pa + sa;
                qb = D_REF*(qb+pb); float sb = (cur.y + A_REF*qb >= THETA) ? 1.f : 0.f; pb = D_REF*pb + sb;
                qc = D_REF*(qc+pc); float sc = (cur.z + A_REF*qc >= THETA) ? 1.f : 0.f; pc = D_REF*pc + sc;
                qd = D_REF*(qd+pd); float sd = (cur.w + A_REF*qd >= THETA) ? 1.f : 0.f; pd = D_REF*pd + sd;

                Qa = D_SR*(Qa+Pa); Pa = D_SR*Pa + sa;
                Qb = D_SR*(Qb+Pb); Pb = D_SR*Pb + sb;
                Qc = D_SR*(Qc+Pc); Pc = D_SR*Pc + sc;
                Qd = D_SR*(Qd+Pd); Pd = D_SR*Pd + sd;
                float vv = GAIN * (((B_SR*Qa + B_SR*Qb) + B_SR*Qc) + B_SR*Qd);

                q2 = D_REF*(q2+p2); float s = (vv + A_REF*q2 >= THETA) ? 1.f : 0.f; p2 = D_REF*p2 + s;
                q3 = D_SR*(q3+p3);  p3 = D_SR*p3 + s;
                ob[(size_t)t * howo] = B_SR * q3;
            }
        }
    }
}

// ---------------- K4: conv2 16->32, 3x3 pad1, 14x14, oc-lanes + FFMA2 -----------
// 224 thr = 7 warps; warp w -> rows {2w,2w+1}; lane = oc; inputs broadcast-read
// Shifted smem copy: A and S pairs are direct aligned LDS.64 (no packing MOVs)
__global__ void __launch_bounds__(224) conv2_kernel() {
    __shared__ float sIn [16 * 256];  // [ic][row16][col16]
    __shared__ float sInS[16 * 256];  // same, columns shifted left by one
    __shared__ float sW[4608];        // [k144][oc32]
    int t = blockIdx.x, n = blockIdx.y, tid = threadIdx.x;

    for (int i = tid; i < 4608; i += 224) sW[i] = WT2[i];
    for (int i = tid; i < 4096; i += 224) { sIn[i] = 0.f; sInS[i] = 0.f; }
    __syncthreads();
    for (int i = tid; i < 16 * 196; i += 224) {
        int c = i / 196, idx = i % 196, ih = idx / 14, iw = idx % 14;
        float v = BUFB[((size_t)(n * 16 + c) * 300 + t) * 196 + idx];
        sIn [c * 256 + (ih + 1) * 16 + (iw + 1)] = v;
        sInS[c * 256 + (ih + 1) * 16 + iw      ] = v;   // sInS[i] = sIn[i+1]
    }
    __syncthreads();

    int wp = tid >> 5, oc = tid & 31;
    ull acc0[7], acc1[7];
    #pragma unroll
    for (int p = 0; p < 7; p++) { acc0[p] = 0ull; acc1[p] = 0ull; }

    for (int ic = 0; ic < 16; ic++) {
        ull wq[9];
        #pragma unroll
        for (int k = 0; k < 9; k++) {
            float wv = sW[(ic * 9 + k) * 32 + oc];
            wq[k] = pk(wv, wv);
        }
        const float* base  = &sIn [ic * 256 + (2 * wp) * 16];
        const float* baseS = &sInS[ic * 256 + (2 * wp) * 16];
        #pragma unroll
        for (int j = 0; j < 4; j++) {
            const ull* ra = reinterpret_cast<const ull*>(base  + j * 16);
            const ull* rs = reinterpret_cast<const ull*>(baseS + j * 16);
            ull A[8], S[7];
            #pragma unroll
            for (int p = 0; p < 8; p++) A[p] = ra[p];   // (x[2p], x[2p+1])
            #pragma unroll
            for (int p = 0; p < 7; p++) S[p] = rs[p];   // (x[2p+1], x[2p+2])

            if (j <= 2) {   // out row 2w, kh = j
                int kb = j * 3;
                #pragma unroll
                for (int p = 0; p < 7; p++) fma2(acc0[p], A[p],   wq[kb+0]);
                #pragma unroll
                for (int p = 0; p < 7; p++) fma2(acc0[p], S[p],   wq[kb+1]);
                #pragma unroll
                for (int p = 0; p < 7; p++) fma2(acc0[p], A[p+1], wq[kb+2]);
            }
            if (j >= 1) {   // out row 2w+1, kh = j-1
                int kb = (j - 1) * 3;
                #pragma unroll
                for (int p = 0; p < 7; p++) fma2(acc1[p], A[p],   wq[kb+0]);
                #pragma unroll
                for (int p = 0; p < 7; p++) fma2(acc1[p], S[p],   wq[kb+1]);
                #pragma unroll
                for (int p = 0; p < 7; p++) fma2(acc1[p], A[p+1], wq[kb+2]);
            }
        }
    }
    // pooled-quad store: quad index = wp*7 + p; full float4 per window
    float4* qb = reinterpret_cast<float4*>(BUFA) +
                 (((size_t)(n * 32 + oc) * 300 + t) * 49 + wp * 7);
    #pragma unroll
    for (int p = 0; p < 7; p++) {
        float2 lo = upk(acc0[p]), hi = upk(acc1[p]);
        qb[p] = make_float4(lo.x, lo.y, hi.x, hi.y);
    }
}

// ---------------- K6: conv3 32->64, 3x3 pad1, 7x7, 2 timesteps/block ------------
// 224 thr = 7 warps; warp = out row; lane -> oc pair (2l,2l+1); weights LDG.64
__global__ void __launch_bounds__(224) conv3_kernel() {
    __shared__ float sIn[2][32][108];   // [tt][ic][9 rows x 12-col stride]
    int tp = blockIdx.x, n = blockIdx.y, tid = threadIdx.x;
    int t0 = 2 * tp;

    for (int i = tid; i < 2 * 32 * 108; i += 224) ((float*)sIn)[i] = 0.f;
    __syncthreads();
    for (int i = tid; i < 2 * 32 * 49; i += 224) {
        int tt = i / (32 * 49), r = i % (32 * 49);
        int c = r / 49, idx = r % 49, ih = idx / 7, iw = idx % 7;
        sIn[tt][c][(ih + 1) * 12 + (iw + 1)] =
            BUFB[((size_t)(n * 32 + c) * 300 + t0 + tt) * 49 + idx];
    }
    __syncthreads();

    int wp = tid >> 5, l = tid & 31;
    ull acc[2][2][4];
    #pragma unroll
    for (int tt = 0; tt < 2; tt++)
        #pragma unroll
        for (int s = 0; s < 2; s++)
            #pragma unroll
            for (int p = 0; p < 4; p++) acc[tt][s][p] = 0ull;

    for (int ic = 0; ic < 32; ic++) {
        ull wa[9], wb[9];
        #pragma unroll
        for (int k = 0; k < 9; k++) {
            float2 wv = *reinterpret_cast<const float2*>(&WT3[(ic * 9 + k) * 64 + 2 * l]);
            wa[k] = pk(wv.x, wv.x);
            wb[k] = pk(wv.y, wv.y);
        }
        #pragma unroll
        for (int tt = 0; tt < 2; tt++) {
            const float* base = &sIn[tt][ic][wp * 12];
            #pragma unroll
            for (int j = 0; j < 3; j++) {     // kh = j
                const float* rp = base + j * 12;
                float4 f0 = *reinterpret_cast<const float4*>(rp);
                float4 f1 = *reinterpret_cast<const float4*>(rp + 4);
                float4 f2 = *reinterpret_cast<const float4*>(rp + 8);
                ull A0=pk(f0.x,f0.y), A1=pk(f0.z,f0.w), A2=pk(f1.x,f1.y),
                    A3=pk(f1.z,f1.w), A4=pk(f2.x,f2.y);
                ull S0=pk(f0.y,f0.z), S1=pk(f0.w,f1.x), S2=pk(f1.y,f1.z), S3=pk(f1.w,f2.x);
                int kb = j * 3;
                ull* a0 = acc[tt][0]; ull* a1 = acc[tt][1];
                fma2(a0[0],A0,wa[kb+0]); fma2(a0[1],A1,wa[kb+0]); fma2(a0[2],A2,wa[kb+0]); fma2(a0[3],A3,wa[kb+0]);
                fma2(a0[0],S0,wa[kb+1]); fma2(a0[1],S1,wa[kb+1]); fma2(a0[2],S2,wa[kb+1]); fma2(a0[3],S3,wa[kb+1]);
                fma2(a0[0],A1,wa[kb+2]); fma2(a0[1],A2,wa[kb+2]); fma2(a0[2],A3,wa[kb+2]); fma2(a0[3],A4,wa[kb+2]);
                fma2(a1[0],A0,wb[kb+0]); fma2(a1[1],A1,wb[kb+0]); fma2(a1[2],A2,wb[kb+0]); fma2(a1[3],A3,wb[kb+0]);
                fma2(a1[0],S0,wb[kb+1]); fma2(a1[1],S1,wb[kb+1]); fma2(a1[2],S2,wb[kb+1]); fma2(a1[3],S3,wb[kb+1]);
                fma2(a1[0],A1,wb[kb+2]); fma2(a1[1],A2,wb[kb+2]); fma2(a1[2],A3,wb[kb+2]); fma2(a1[3],A4,wb[kb+2]);
            }
        }
    }
    #pragma unroll
    for (int tt = 0; tt < 2; tt++)
        #pragma unroll
        for (int s = 0; s < 2; s++) {
            float* dst = BUFA + ((size_t)(n * 64 + 2 * l + s) * 300 + t0 + tt) * 49 + wp * 7;
            float2 v0 = upk(acc[tt][s][0]), v1 = upk(acc[tt][s][1]);
            float2 v2 = upk(acc[tt][s][2]), v3 = upk(acc[tt][s][3]);
            dst[0]=v0.x; dst[1]=v0.y; dst[2]=v1.x; dst[3]=v1.y;
            dst[4]=v2.x; dst[5]=v2.y; dst[6]=v3.x;
        }
}

// ---------------- K7: spike(u5) then psp -> P5, in place; ring prefetch ---------
__global__ void spikepsp_kernel(int HW, int total) {
    int tid = blockIdx.x * blockDim.x + threadIdx.x;
    if (tid >= total) return;
    int slab = tid / HW, hw = tid % HW;
    float* bp = BUFA + (size_t)slab * 300 * HW + hw;
    float pr = 0.f, qr = 0.f, pp = 0.f, qp = 0.f;

    float ring[8];
    #pragma unroll
    for (int i = 0; i < 8; i++) ring[i] = bp[(size_t)i * HW];

    for (int tb = 0; tb < 300; tb += 8) {
        #pragma unroll
        for (int j = 0; j < 8; j++) {
            int t = tb + j;
            if (t < 300) {
                float cur = ring[j];
                if (t + 8 < 300) ring[j] = bp[(size_t)(t + 8) * HW];
                qr = D_REF * (qr + pr);
                float s = (cur + A_REF * qr >= THETA) ? 1.f : 0.f;
                pr = D_REF * pr + s;
                qp = D_SR * (qp + pp);
                pp = D_SR * pp + s;
                bp[(size_t)t * HW] = B_SR * qp;
            }
        }
    }
}

// ---------------- K8: dense 64*7*7 -> 10, 4 timesteps/block ---------------------
__global__ void __launch_bounds__(320) dense_kernel(const float* __restrict__ w,
                                                    float* __restrict__ out) {
    __shared__ float sX[4][3136];
    int tp = blockIdx.x, n = blockIdx.y, tid = threadIdx.x;
    int t0 = 4 * tp;
    for (int i = tid; i < 4 * 3136; i += 320) {
        int tt = i / 3136, j = i % 3136, c = j / 49, hw = j % 49;
        sX[tt][j] = BUFA[((size_t)(n * 64 + c) * 300 + t0 + tt) * 49 + hw];
    }
    __syncthreads();
    int wp = tid / 32, lane = tid % 32;
    const float* wrow = w + (size_t)wp * 3136;
    float s0 = 0.f, s1 = 0.f, s2 = 0.f, s3 = 0.f;
    #pragma unroll
    for (int k = 0; k < 98; k++) {
        int idx = lane + k * 32;
        float wv = __ldg(wrow + idx);
        s0 += sX[0][idx] * wv;
        s1 += sX[1][idx] * wv;
        s2 += sX[2][idx] * wv;
        s3 += sX[3][idx] * wv;
    }
    #pragma unroll
    for (int o = 16; o > 0; o >>= 1) {
        s0 += __shfl_down_sync(0xffffffff, s0, o);
        s1 += __shfl_down_sync(0xffffffff, s1, o);
        s2 += __shfl_down_sync(0xffffffff, s2, o);
        s3 += __shfl_down_sync(0xffffffff, s3, o);
    }
    if (lane == 0) {
        float* op = out + (size_t)n * 3000 + wp * 300 + t0;
        op[0] = s0; op[1] = s1; op[2] = s2; op[3] = s3;
    }
}

// ---------------- K9: final spike, in place on d_out; float4 ring ---------------
__global__ void spike_out_kernel(float* __restrict__ out) {
    int tid = threadIdx.x;
    if (tid >= 80) return;
    float4* bp4 = reinterpret_cast<float4*>(out + (size_t)tid * 300);
    float p = 0.f, q = 0.f;

    float4 ring[4];
    #pragma unroll
    for (int i = 0; i < 4; i++) ring[i] = bp4[i];
    for (int cb = 0; cb < 75; cb += 4) {
        #pragma unroll
        for (int j = 0; j < 4; j++) {
            int c = cb + j;
            if (c < 75) {
                float4 cur = ring[j];
                if (c + 4 < 75) ring[j] = bp4[c + 4];
                float4 so;
                q = D_REF*(q+p); so.x = (cur.x + A_REF*q >= THETA) ? 1.f : 0.f; p = D_REF*p + so.x;
                q = D_REF*(q+p); so.y = (cur.y + A_REF*q >= THETA) ? 1.f : 0.f; p = D_REF*p + so.y;
                q = D_REF*(q+p); so.z = (cur.z + A_REF*q >= THETA) ? 1.f : 0.f; p = D_REF*p + so.z;
                q = D_REF*(q+p); so.w = (cur.w + A_REF*q >= THETA) ? 1.f : 0.f; p = D_REF*p + so.w;
                bp4[c] = so;
            }
        }
    }
}

// ---------------- launcher ------------------------------------------------------
extern "C" void kernel_launch(void* const* d_in, const int* in_sizes, int n_in,
                              void* d_out, int out_size) {
    const float* x   = (const float*)d_in[0];   // [8,1,30,30,300]
    const float* w1  = (const float*)d_in[1];   // [16,1,5,5]
    const float* w2  = (const float*)d_in[2];   // [32,16,3,3]
    const float* w3  = (const float*)d_in[3];   // [64,32,3,3]
    const float* wfc = (const float*)d_in[4];   // [10,64,7,7]
    float* out = (float*)d_out;                 // [8,10,300]

    dim3 gconv(300, 8);
    dim3 ghalf(150, 8);
    dim3 gquar(75, 8);

    wprep_kernel<<<72, 256>>>(w2, w3);
    psp_in_kernel<<<113, 64>>>(x);                       // P0 -> BUFB
    conv1_kernel<<<gconv, 448>>>(w1);                    // U1 quads -> BUFA
    poolfuse_kernel<<<392, 64>>>(196, 8 * 16 * 196);     // P2 -> BUFB
    conv2_kernel<<<gconv, 224>>>();                      // U3 quads -> BUFA
    poolfuse_kernel<<<196, 64>>>(49, 8 * 32 * 49);       // P4 -> BUFB
    conv3_kernel<<<ghalf, 224>>>();                      // U5 -> BUFA
    spikepsp_kernel<<<392, 64>>>(49, 8 * 64 * 49);       // P5 in place
    dense_kernel<<<gquar, 320>>>(wfc, out);
    spike_out_kernel<<<1, 96>>>(out);
}